// round 5
// baseline (speedup 1.0000x reference)
#include <cuda_runtime.h>
#include <cstdint>

// Problem constants
#define C_DIM 1024
#define B_DIM 4
#define T_DIM 2048
#define H_DIM 16
#define DH_DIM 64
#define M_DIM (B_DIM * T_DIM)   // 8192

// ---------------------------------------------------------------------------
// Scratch (no cudaMalloc allowed -> __device__ globals)
// ---------------------------------------------------------------------------
__device__ float g_Wq [C_DIM * C_DIM];   // W_eff[c][h*64+d] row-major
__device__ float g_Wk [C_DIM * C_DIM];
__device__ float g_Wv [C_DIM * C_DIM];
__device__ float g_WoT[C_DIM * C_DIM];   // Wo^T row-major: [c][j] = Wo[j][c]
__device__ float g_Q  [M_DIM * C_DIM];   // [B,T,H*DH]
__device__ float g_K  [M_DIM * C_DIM];
__device__ float g_V  [M_DIM * C_DIM];
__device__ float g_att[M_DIM * C_DIM];   // attention output, [B,T,C]

// ---------------------------------------------------------------------------
// Weight prep: gather [H,C,DH] -> row-major [C, H*DH]; transpose Wo.
// ---------------------------------------------------------------------------
__global__ void prep_weights(const float* __restrict__ Wq,
                             const float* __restrict__ Wk,
                             const float* __restrict__ Wv,
                             const float* __restrict__ Wo)
{
    int i = blockIdx.x * blockDim.x + threadIdx.x;   // over C*C
    int c = i >> 10;
    int n = i & 1023;
    int h = n >> 6;
    int d = n & 63;
    int src = (h << 16) + (c << 6) + d;              // h*C*DH + c*DH + d
    g_Wq[i]  = Wq[src];
    g_Wk[i]  = Wk[src];
    g_Wv[i]  = Wv[src];
    g_WoT[i] = Wo[n * C_DIM + c];
}

// ---------------------------------------------------------------------------
// SGEMM: C = A[MxK] * B[KxN] (+ bias), row-major.
// 128x128 block tile, BK=8, 256 threads, 8x8 micro-tile (split quadrants).
// ---------------------------------------------------------------------------
#define BM 128
#define BN 128
#define BK 8

__global__ __launch_bounds__(256)
void sgemm128(const float* __restrict__ A, const float* __restrict__ B,
              float* __restrict__ Cmat, const float* __restrict__ bias,
              int M, int N, int K)
{
    __shared__ float As[BK][BM + 4];   // +4 pad -> conflict-free transposed store
    __shared__ float Bs[BK][BN];

    const int tid = threadIdx.x;
    const int tx  = tid & 15;
    const int ty  = tid >> 4;

    const int arow = tid >> 1;
    const int acol = (tid & 1) << 2;
    const int brow = tid >> 5;
    const int bcol = (tid & 31) << 2;

    const float* Aptr = A + (size_t)(blockIdx.y * BM + arow) * K + acol;
    const float* Bptr = B + (size_t)brow * N + blockIdx.x * BN + bcol;

    float acc[8][8];
#pragma unroll
    for (int i = 0; i < 8; i++)
#pragma unroll
        for (int j = 0; j < 8; j++) acc[i][j] = 0.f;

    for (int k0 = 0; k0 < K; k0 += BK) {
        float4 av = *(const float4*)(Aptr + k0);
        float4 bv = *(const float4*)(Bptr + (size_t)k0 * N);
        As[acol + 0][arow] = av.x;
        As[acol + 1][arow] = av.y;
        As[acol + 2][arow] = av.z;
        As[acol + 3][arow] = av.w;
        *(float4*)&Bs[brow][bcol] = bv;
        __syncthreads();

#pragma unroll
        for (int k = 0; k < BK; k++) {
            float a[8], b[8];
            *(float4*)&a[0] = *(const float4*)&As[k][ty * 4];
            *(float4*)&a[4] = *(const float4*)&As[k][64 + ty * 4];
            *(float4*)&b[0] = *(const float4*)&Bs[k][tx * 4];
            *(float4*)&b[4] = *(const float4*)&Bs[k][64 + tx * 4];
#pragma unroll
            for (int i = 0; i < 8; i++)
#pragma unroll
                for (int j = 0; j < 8; j++)
                    acc[i][j] = fmaf(a[i], b[j], acc[i][j]);
        }
        __syncthreads();
    }

    const int row0 = blockIdx.y * BM;
    const int col0 = blockIdx.x * BN;
#pragma unroll
    for (int iq = 0; iq < 2; iq++) {
#pragma unroll
        for (int i = 0; i < 4; i++) {
            int r = row0 + iq * 64 + ty * 4 + i;
#pragma unroll
            for (int jq = 0; jq < 2; jq++) {
                int c = col0 + jq * 64 + tx * 4;
                float4 v;
                v.x = acc[iq * 4 + i][jq * 4 + 0];
                v.y = acc[iq * 4 + i][jq * 4 + 1];
                v.z = acc[iq * 4 + i][jq * 4 + 2];
                v.w = acc[iq * 4 + i][jq * 4 + 3];
                if (bias) {
                    v.x += bias[c + 0];
                    v.y += bias[c + 1];
                    v.z += bias[c + 2];
                    v.w += bias[c + 3];
                }
                *(float4*)&Cmat[(size_t)r * N + c] = v;
            }
        }
    }
}

// ---------------------------------------------------------------------------
// Flash attention (causal), fp32. One block per (q-tile of 64, head, batch).
// 256 threads = 16x16; each thread owns a 4x4 S fragment and a 4x4 O fragment.
//
// K tile lives at pitch 64 with an XOR swizzle on the float4 column:
//   phys_col4 = d4 ^ (row & 7)
// In the S-phase, the 8 lanes of one LDS.128 phase read rows j*16+tx
// (tx & 7 distinct), giving start banks 4*((d4^tx)&7) — a permutation of
// {0,4,...,28}: conflict-free without any pitch padding.
// Shared: Qs[64][64] | KP[64][64] (K tile, reused as P) | Vs[64][64]
//       = 49152 B static -> no dynamic-smem attribute needed.
// ---------------------------------------------------------------------------
__global__ __launch_bounds__(256)
void attn_kernel(const float* __restrict__ Q, const float* __restrict__ K,
                 const float* __restrict__ V, float* __restrict__ Oa)
{
    __shared__ float Qs[64 * 64];
    __shared__ float KP[64 * 64];
    __shared__ float Vs[64 * 64];

    const int qt  = blockIdx.x;         // 0..31
    const int h   = blockIdx.y;         // 0..15
    const int b   = blockIdx.z;         // 0..3
    const int tid = threadIdx.x;
    const int tx  = tid & 15;
    const int ty  = tid >> 4;
    const int q_lo = ty * 4;            // local query rows q_lo..q_lo+3

    // Load Q tile (coalesced float4)
    const float* qbase = Q + (size_t)(b * T_DIM + qt * 64) * C_DIM + h * DH_DIM;
#pragma unroll
    for (int f = tid; f < 1024; f += 256) {
        int r  = f >> 4;
        int dc = (f & 15) << 2;
        *(float4*)&Qs[r * 64 + dc] = *(const float4*)(qbase + (size_t)r * C_DIM + dc);
    }

    float m_i[4], l_i[4], acc[4][4];
#pragma unroll
    for (int i = 0; i < 4; i++) {
        m_i[i] = -1e30f;
        l_i[i] = 0.f;
#pragma unroll
        for (int j = 0; j < 4; j++) acc[i][j] = 0.f;
    }

    for (int kt = 0; kt <= qt; kt++) {
        __syncthreads();   // previous iteration done reading KP/Vs

        const float* kb = K + (size_t)(b * T_DIM + kt * 64) * C_DIM + h * DH_DIM;
        const float* vb = V + (size_t)(b * T_DIM + kt * 64) * C_DIM + h * DH_DIM;
#pragma unroll
        for (int f = tid; f < 1024; f += 256) {
            int r  = f >> 4;
            int d4 = f & 15;
            int sw = (d4 ^ (r & 7)) << 2;               // swizzled K store
            *(float4*)&KP[r * 64 + sw] = *(const float4*)(kb + (size_t)r * C_DIM + (d4 << 2));
            *(float4*)&Vs[r * 64 + (d4 << 2)] = *(const float4*)(vb + (size_t)r * C_DIM + (d4 << 2));
        }
        __syncthreads();

        // S = Q * K^T (64 d, float4-vectorized)
        float s[4][4];
#pragma unroll
        for (int i = 0; i < 4; i++)
#pragma unroll
            for (int j = 0; j < 4; j++) s[i][j] = 0.f;

#pragma unroll
        for (int d4 = 0; d4 < 16; d4++) {
            const int ksw = (d4 ^ (tx & 7)) << 2;       // row = j*16+tx -> row&7 == tx&7
            float4 q[4], kf[4];
#pragma unroll
            for (int i = 0; i < 4; i++)
                q[i] = *(const float4*)&Qs[(q_lo + i) * 64 + (d4 << 2)];
#pragma unroll
            for (int j = 0; j < 4; j++)
                kf[j] = *(const float4*)&KP[(j * 16 + tx) * 64 + ksw];
#pragma unroll
            for (int i = 0; i < 4; i++)
#pragma unroll
                for (int j = 0; j < 4; j++) {
                    s[i][j] = fmaf(q[i].x, kf[j].x, s[i][j]);
                    s[i][j] = fmaf(q[i].y, kf[j].y, s[i][j]);
                    s[i][j] = fmaf(q[i].z, kf[j].z, s[i][j]);
                    s[i][j] = fmaf(q[i].w, kf[j].w, s[i][j]);
                }
        }

        // scale + causal mask (only bites on diagonal tile)
#pragma unroll
        for (int i = 0; i < 4; i++)
#pragma unroll
            for (int j = 0; j < 4; j++) {
                s[i][j] *= 0.125f;   // DH^-0.5
                int kg = kt * 64 + j * 16 + tx;
                int qg = qt * 64 + q_lo + i;
                if (kg > qg) s[i][j] = -1e30f;
            }

        // online softmax: rows are owned by 16 consecutive lanes (same ty)
        float p[4][4];
#pragma unroll
        for (int i = 0; i < 4; i++) {
            float mx = fmaxf(fmaxf(s[i][0], s[i][1]), fmaxf(s[i][2], s[i][3]));
#pragma unroll
            for (int off = 1; off < 16; off <<= 1)
                mx = fmaxf(mx, __shfl_xor_sync(0xffffffffu, mx, off));
            float mnew = fmaxf(m_i[i], mx);
            float corr = __expf(m_i[i] - mnew);
            m_i[i] = mnew;
            float rs = 0.f;
#pragma unroll
            for (int j = 0; j < 4; j++) {
                p[i][j] = __expf(s[i][j] - mnew);
                rs += p[i][j];
            }
#pragma unroll
            for (int off = 1; off < 16; off <<= 1)
                rs += __shfl_xor_sync(0xffffffffu, rs, off);
            l_i[i] = l_i[i] * corr + rs;
#pragma unroll
            for (int j = 0; j < 4; j++) acc[i][j] *= corr;
        }

        // write P into the K buffer, UNswizzled (K no longer needed)
        __syncthreads();
#pragma unroll
        for (int i = 0; i < 4; i++)
#pragma unroll
            for (int j = 0; j < 4; j++)
                KP[(q_lo + i) * 64 + j * 16 + tx] = p[i][j];
        __syncthreads();

        // O += P * V (P reads are row-broadcast within a half-warp)
#pragma unroll
        for (int k4 = 0; k4 < 16; k4++) {
            float4 pv[4];
#pragma unroll
            for (int i = 0; i < 4; i++)
                pv[i] = *(const float4*)&KP[(q_lo + i) * 64 + k4 * 4];
            float4 v0 = *(const float4*)&Vs[(k4 * 4 + 0) * 64 + tx * 4];
            float4 v1 = *(const float4*)&Vs[(k4 * 4 + 1) * 64 + tx * 4];
            float4 v2 = *(const float4*)&Vs[(k4 * 4 + 2) * 64 + tx * 4];
            float4 v3 = *(const float4*)&Vs[(k4 * 4 + 3) * 64 + tx * 4];
#pragma unroll
            for (int i = 0; i < 4; i++) {
                acc[i][0] = fmaf(pv[i].x, v0.x, acc[i][0]);
                acc[i][1] = fmaf(pv[i].x, v0.y, acc[i][1]);
                acc[i][2] = fmaf(pv[i].x, v0.z, acc[i][2]);
                acc[i][3] = fmaf(pv[i].x, v0.w, acc[i][3]);
                acc[i][0] = fmaf(pv[i].y, v1.x, acc[i][0]);
                acc[i][1] = fmaf(pv[i].y, v1.y, acc[i][1]);
                acc[i][2] = fmaf(pv[i].y, v1.z, acc[i][2]);
                acc[i][3] = fmaf(pv[i].y, v1.w, acc[i][3]);
                acc[i][0] = fmaf(pv[i].z, v2.x, acc[i][0]);
                acc[i][1] = fmaf(pv[i].z, v2.y, acc[i][1]);
                acc[i][2] = fmaf(pv[i].z, v2.z, acc[i][2]);
                acc[i][3] = fmaf(pv[i].z, v2.w, acc[i][3]);
                acc[i][0] = fmaf(pv[i].w, v3.x, acc[i][0]);
                acc[i][1] = fmaf(pv[i].w, v3.y, acc[i][1]);
                acc[i][2] = fmaf(pv[i].w, v3.z, acc[i][2]);
                acc[i][3] = fmaf(pv[i].w, v3.w, acc[i][3]);
            }
        }
    }

    // normalize + write: [B,T, h*64 + d]
    float* ob = Oa + (size_t)(b * T_DIM + qt * 64) * C_DIM + h * DH_DIM;
#pragma unroll
    for (int i = 0; i < 4; i++) {
        float inv = 1.f / l_i[i];
        float4 o;
        o.x = acc[i][0] * inv;
        o.y = acc[i][1] * inv;
        o.z = acc[i][2] * inv;
        o.w = acc[i][3] * inv;
        *(float4*)&ob[(size_t)(q_lo + i) * C_DIM + tx * 4] = o;
    }
}

// ---------------------------------------------------------------------------
// Launch
// ---------------------------------------------------------------------------
extern "C" void kernel_launch(void* const* d_in, const int* in_sizes, int n_in,
                              void* d_out, int out_size)
{
    (void)in_sizes; (void)n_in; (void)out_size;
    const float* x  = (const float*)d_in[0];
    const float* Wq = (const float*)d_in[1];
    const float* Wk = (const float*)d_in[2];
    const float* Wv = (const float*)d_in[3];
    const float* Wo = (const float*)d_in[4];
    const float* bo = (const float*)d_in[5];
    float* out = (float*)d_out;

    float *pWq, *pWk, *pWv, *pWoT, *pQ, *pK, *pV, *pAtt;
    cudaGetSymbolAddress((void**)&pWq,  g_Wq);
    cudaGetSymbolAddress((void**)&pWk,  g_Wk);
    cudaGetSymbolAddress((void**)&pWv,  g_Wv);
    cudaGetSymbolAddress((void**)&pWoT, g_WoT);
    cudaGetSymbolAddress((void**)&pQ,   g_Q);
    cudaGetSymbolAddress((void**)&pK,   g_K);
    cudaGetSymbolAddress((void**)&pV,   g_V);
    cudaGetSymbolAddress((void**)&pAtt, g_att);

    // 1. weight prep
    prep_weights<<<(C_DIM * C_DIM) / 256, 256>>>(Wq, Wk, Wv, Wo);

    // 2. QKV projections
    dim3 gg(C_DIM / BN, M_DIM / BM);
    sgemm128<<<gg, 256>>>(x, pWq, pQ, nullptr, M_DIM, C_DIM, C_DIM);
    sgemm128<<<gg, 256>>>(x, pWk, pK, nullptr, M_DIM, C_DIM, C_DIM);
    sgemm128<<<gg, 256>>>(x, pWv, pV, nullptr, M_DIM, C_DIM, C_DIM);

    // 3. causal flash attention (48 KB static shared, no attribute needed)
    attn_kernel<<<dim3(T_DIM / 64, H_DIM, B_DIM), 256>>>(pQ, pK, pV, pAtt);

    // 4. output projection + bias
    sgemm128<<<gg, 256>>>(pAtt, pWoT, out, bo, M_DIM, C_DIM, C_DIM);
}

// round 7
// speedup vs baseline: 1.5163x; 1.5163x over previous
#include <cuda_runtime.h>
#include <cuda_bf16.h>
#include <cstdint>

// Problem constants
#define C_DIM 1024
#define B_DIM 4
#define T_DIM 2048
#define H_DIM 16
#define DH_DIM 64
#define M_DIM (B_DIM * T_DIM)   // 8192

// ===========================================================================
// Scratch (__device__ globals; no cudaMalloc allowed)
// ===========================================================================
__device__ float          g_Q  [M_DIM * C_DIM];   // fp32 [B,T,H*DH]
__device__ float          g_K  [M_DIM * C_DIM];
__device__ float          g_V  [M_DIM * C_DIM];
__device__ float          g_att[M_DIM * C_DIM];
__device__ __nv_bfloat16  g_Xh [M_DIM * C_DIM];   // x hi/lo split
__device__ __nv_bfloat16  g_Xl [M_DIM * C_DIM];
__device__ __nv_bfloat16  g_Ah [M_DIM * C_DIM];   // attention output split
__device__ __nv_bfloat16  g_Al [M_DIM * C_DIM];
// weights as [N][K] bf16 hi/lo (B operand of mma .col = K-major [N,K] rows)
__device__ __nv_bfloat16  g_Wqh[C_DIM * C_DIM], g_Wql[C_DIM * C_DIM];
__device__ __nv_bfloat16  g_Wkh[C_DIM * C_DIM], g_Wkl[C_DIM * C_DIM];
__device__ __nv_bfloat16  g_Wvh[C_DIM * C_DIM], g_Wvl[C_DIM * C_DIM];
__device__ __nv_bfloat16  g_Woh[C_DIM * C_DIM], g_Wol[C_DIM * C_DIM];

__device__ __forceinline__ void split_bf16(float v, __nv_bfloat16& h, __nv_bfloat16& l) {
    __nv_bfloat16 hi = __float2bfloat16(v);
    h = hi;
    l = __float2bfloat16(v - __bfloat162float(hi));
}

// ---------------------------------------------------------------------------
// Weight prep: [H,C,DH] -> [n=h*64+d][c] bf16 hi/lo; Wo [j][c] is already [N][K].
// ---------------------------------------------------------------------------
__global__ void prep_weights(const float* __restrict__ Wq,
                             const float* __restrict__ Wk,
                             const float* __restrict__ Wv,
                             const float* __restrict__ Wo)
{
    int i = blockIdx.x * blockDim.x + threadIdx.x;   // i = n*1024 + c
    int n = i >> 10;
    int c = i & 1023;
    int h = n >> 6;
    int d = n & 63;
    int src = (h << 16) + (c << 6) + d;              // h*C*DH + c*DH + d
    split_bf16(Wq[src], g_Wqh[i], g_Wql[i]);
    split_bf16(Wk[src], g_Wkh[i], g_Wkl[i]);
    split_bf16(Wv[src], g_Wvh[i], g_Wvl[i]);
    split_bf16(Wo[i],   g_Woh[i], g_Wol[i]);
}

__global__ void split_x(const float* __restrict__ x)
{
    int i = blockIdx.x * blockDim.x + threadIdx.x;
    split_bf16(x[i], g_Xh[i], g_Xl[i]);
}

__global__ void split_att()
{
    int i = blockIdx.x * blockDim.x + threadIdx.x;
    split_bf16(g_att[i], g_Ah[i], g_Al[i]);
}

// ===========================================================================
// PTX wrappers (all plain sm_80+ — assemble under compute_103)
// ===========================================================================
__device__ __forceinline__ uint32_t smem_u32(const void* p) {
    uint32_t a;
    asm("{ .reg .u64 t; cvta.to.shared.u64 t, %1; cvt.u32.u64 %0, t; }"
        : "=r"(a) : "l"(p));
    return a;
}
__device__ __forceinline__ void ldsm4(uint32_t* r, uint32_t addr) {
    asm volatile("ldmatrix.sync.aligned.m8n8.x4.shared.b16 {%0,%1,%2,%3}, [%4];"
                 : "=r"(r[0]), "=r"(r[1]), "=r"(r[2]), "=r"(r[3]) : "r"(addr));
}
__device__ __forceinline__ void mma16816(float* c, const uint32_t* a, const uint32_t* b) {
    asm volatile("mma.sync.aligned.m16n8k16.row.col.f32.bf16.bf16.f32 "
                 "{%0,%1,%2,%3}, {%4,%5,%6,%7}, {%8,%9}, {%0,%1,%2,%3};"
                 : "+f"(c[0]), "+f"(c[1]), "+f"(c[2]), "+f"(c[3])
                 : "r"(a[0]), "r"(a[1]), "r"(a[2]), "r"(a[3]),
                   "r"(b[0]), "r"(b[1]));
}
#define CP_ASYNC16(saddr, gptr) \
    asm volatile("cp.async.cg.shared.global [%0], [%1], 16;" \
                 :: "r"(saddr), "l"(gptr) : "memory")
#define CP_COMMIT()  asm volatile("cp.async.commit_group;" ::: "memory")
#define CP_WAIT0()   asm volatile("cp.async.wait_group 0;" ::: "memory")

// ===========================================================================
// bf16 hi/lo GEMM via mma.sync: C[M,N] = A[M,K] * B[N,K]^T (+bias), fp32 out.
// Block 128x128, 8 warps (4m x 2n), warp tile 32x64. K-chunk 32.
// SMEM tiles at pitch 80B: ldmatrix 8-row column reads hit banks 20r mod 32 =
// {0,20,8,28,16,4,24,12} -> conflict-free, no swizzle. 40KB static shared.
// Per k16 step: 3 compensated HMMA terms (AhBh + AhBl + AlBh).
// ===========================================================================
#define PITCH   80
#define TILE_B  (128 * PITCH)          // 10240 bytes per tile
#define OA_H    0
#define OA_L    (TILE_B)
#define OB_H    (2 * TILE_B)
#define OB_L    (3 * TILE_B)

__global__ __launch_bounds__(256, 2)
void gemm_mma(const __nv_bfloat16* __restrict__ Ah, const __nv_bfloat16* __restrict__ Al,
              const __nv_bfloat16* __restrict__ Bh, const __nv_bfloat16* __restrict__ Bl,
              float* __restrict__ Cmat, const float* __restrict__ bias,
              int Nglob, int Kglob)
{
    __shared__ char sm[4 * TILE_B];    // 40960 B static
    const uint32_t sb = smem_u32(sm);

    const int tid  = threadIdx.x;
    const int lane = tid & 31;
    const int wid  = tid >> 5;
    const int wm   = wid & 3;          // warp row 0..3  (32 rows each)
    const int wn   = wid >> 2;         // warp col 0..1  (64 cols each)

    const int row0 = blockIdx.y * 128;
    const int col0 = blockIdx.x * 128;

    // gmem load mapping: thread covers 16B blocks u = tid, tid+256 of each tile
    const int r0g = tid >> 2;                 // row   of block u0 (0..63)
    const int c0g = tid & 3;                  // 16B col of block u0 (0..3)
    // u1 = tid+256 -> row += 64, same col
    const __nv_bfloat16* pAh0 = Ah + (size_t)(row0 + r0g) * Kglob + c0g * 8;
    const __nv_bfloat16* pAl0 = Al + (size_t)(row0 + r0g) * Kglob + c0g * 8;
    const __nv_bfloat16* pBh0 = Bh + (size_t)(col0 + r0g) * Kglob + c0g * 8;
    const __nv_bfloat16* pBl0 = Bl + (size_t)(col0 + r0g) * Kglob + c0g * 8;
    const size_t rowStep = (size_t)64 * Kglob;
    const uint32_t s0 = (uint32_t)(r0g * PITCH + c0g * 16);
    const uint32_t s1 = s0 + 64 * PITCH;

    // ldmatrix lane address components
    const int a_row = (lane & 7) + ((lane >> 3) & 1) * 8;   // 0..15
    const int a_kb  = (lane >> 4);                          // col half 0/1
    const int b_row = (lane & 7) + ((lane >> 4) & 1) * 8;   // n within pair
    const int b_kb  = (lane >> 3) & 1;                      // k half 0/1

    float acc[2][8][4];
#pragma unroll
    for (int mi = 0; mi < 2; mi++)
#pragma unroll
        for (int nf = 0; nf < 8; nf++)
#pragma unroll
            for (int e = 0; e < 4; e++) acc[mi][nf][e] = 0.f;

    const int NCH = Kglob >> 5;        // chunks of 32
    for (int ch = 0; ch < NCH; ch++) {
        const int k0 = ch << 5;
        __syncthreads();               // everyone done reading previous chunk

        CP_ASYNC16(sb + OA_H + s0, pAh0 + k0);
        CP_ASYNC16(sb + OA_H + s1, pAh0 + rowStep + k0);
        CP_ASYNC16(sb + OA_L + s0, pAl0 + k0);
        CP_ASYNC16(sb + OA_L + s1, pAl0 + rowStep + k0);
        CP_ASYNC16(sb + OB_H + s0, pBh0 + k0);
        CP_ASYNC16(sb + OB_H + s1, pBh0 + rowStep + k0);
        CP_ASYNC16(sb + OB_L + s0, pBl0 + k0);
        CP_ASYNC16(sb + OB_L + s1, pBl0 + rowStep + k0);
        CP_COMMIT();
        CP_WAIT0();
        __syncthreads();

#pragma unroll
        for (int ks = 0; ks < 2; ks++) {
            uint32_t ah[2][4], al[2][4], bh[4][4], bl[4][4];
#pragma unroll
            for (int mi = 0; mi < 2; mi++) {
                uint32_t ar = sb + (uint32_t)((wm * 32 + mi * 16 + a_row) * PITCH
                                              + (2 * ks + a_kb) * 16);
                ldsm4(ah[mi], ar + OA_H);
                ldsm4(al[mi], ar + OA_L);
            }
#pragma unroll
            for (int p = 0; p < 4; p++) {
                uint32_t br = sb + (uint32_t)((wn * 64 + p * 16 + b_row) * PITCH
                                              + (2 * ks + b_kb) * 16);
                ldsm4(bh[p], br + OB_H);
                ldsm4(bl[p], br + OB_L);
            }
#pragma unroll
            for (int mi = 0; mi < 2; mi++)
#pragma unroll
                for (int p = 0; p < 4; p++) {
                    // pair p covers n-frags 2p (regs 0,1) and 2p+1 (regs 2,3)
                    mma16816(acc[mi][2 * p + 0], ah[mi], &bh[p][0]);
                    mma16816(acc[mi][2 * p + 0], ah[mi], &bl[p][0]);
                    mma16816(acc[mi][2 * p + 0], al[mi], &bh[p][0]);
                    mma16816(acc[mi][2 * p + 1], ah[mi], &bh[p][2]);
                    mma16816(acc[mi][2 * p + 1], ah[mi], &bl[p][2]);
                    mma16816(acc[mi][2 * p + 1], al[mi], &bh[p][2]);
                }
        }
    }

    // epilogue: c0,c1 -> (row tq, cols 2*tr..+1); c2,c3 -> row tq+8
    const int tq = lane >> 2;
    const int tr = lane & 3;
#pragma unroll
    for (int mi = 0; mi < 2; mi++) {
        int rbase = row0 + wm * 32 + mi * 16 + tq;
#pragma unroll
        for (int nf = 0; nf < 8; nf++) {
            int col = col0 + wn * 64 + nf * 8 + tr * 2;
            float bx = 0.f, by = 0.f;
            if (bias) { bx = bias[col]; by = bias[col + 1]; }
            float2 v0 = { acc[mi][nf][0] + bx, acc[mi][nf][1] + by };
            float2 v1 = { acc[mi][nf][2] + bx, acc[mi][nf][3] + by };
            *(float2*)&Cmat[(size_t)rbase * Nglob + col]       = v0;
            *(float2*)&Cmat[(size_t)(rbase + 8) * Nglob + col] = v1;
        }
    }
}

// ===========================================================================
// Flash attention (causal), fp32 — unchanged from the passing R5 kernel.
// 64x64 tiles, 256 threads, XOR-swizzled K buffer, 48KB static shared.
// ===========================================================================
__global__ __launch_bounds__(256)
void attn_kernel(const float* __restrict__ Q, const float* __restrict__ K,
                 const float* __restrict__ V, float* __restrict__ Oa)
{
    __shared__ float Qs[64 * 64];
    __shared__ float KP[64 * 64];
    __shared__ float Vs[64 * 64];

    const int qt  = blockIdx.x;
    const int h   = blockIdx.y;
    const int b   = blockIdx.z;
    const int tid = threadIdx.x;
    const int tx  = tid & 15;
    const int ty  = tid >> 4;
    const int q_lo = ty * 4;

    const float* qbase = Q + (size_t)(b * T_DIM + qt * 64) * C_DIM + h * DH_DIM;
#pragma unroll
    for (int f = tid; f < 1024; f += 256) {
        int r  = f >> 4;
        int dc = (f & 15) << 2;
        *(float4*)&Qs[r * 64 + dc] = *(const float4*)(qbase + (size_t)r * C_DIM + dc);
    }

    float m_i[4], l_i[4], acc[4][4];
#pragma unroll
    for (int i = 0; i < 4; i++) {
        m_i[i] = -1e30f;
        l_i[i] = 0.f;
#pragma unroll
        for (int j = 0; j < 4; j++) acc[i][j] = 0.f;
    }

    for (int kt = 0; kt <= qt; kt++) {
        __syncthreads();

        const float* kb = K + (size_t)(b * T_DIM + kt * 64) * C_DIM + h * DH_DIM;
        const float* vb = V + (size_t)(b * T_DIM + kt * 64) * C_DIM + h * DH_DIM;
#pragma unroll
        for (int f = tid; f < 1024; f += 256) {
            int r  = f >> 4;
            int d4 = f & 15;
            int sw = (d4 ^ (r & 7)) << 2;
            *(float4*)&KP[r * 64 + sw] = *(const float4*)(kb + (size_t)r * C_DIM + (d4 << 2));
            *(float4*)&Vs[r * 64 + (d4 << 2)] = *(const float4*)(vb + (size_t)r * C_DIM + (d4 << 2));
        }
        __syncthreads();

        float s[4][4];
#pragma unroll
        for (int i = 0; i < 4; i++)
#pragma unroll
            for (int j = 0; j < 4; j++) s[i][j] = 0.f;

#pragma unroll
        for (int d4 = 0; d4 < 16; d4++) {
            const int ksw = (d4 ^ (tx & 7)) << 2;
            float4 q[4], kf[4];
#pragma unroll
            for (int i = 0; i < 4; i++)
                q[i] = *(const float4*)&Qs[(q_lo + i) * 64 + (d4 << 2)];
#pragma unroll
            for (int j = 0; j < 4; j++)
                kf[j] = *(const float4*)&KP[(j * 16 + tx) * 64 + ksw];
#pragma unroll
            for (int i = 0; i < 4; i++)
#pragma unroll
                for (int j = 0; j < 4; j++) {
                    s[i][j] = fmaf(q[i].x, kf[j].x, s[i][j]);
                    s[i][j] = fmaf(q[i].y, kf[j].y, s[i][j]);
                    s[i][j] = fmaf(q[i].z, kf[j].z, s[i][j]);
                    s[i][j] = fmaf(q[i].w, kf[j].w, s[i][j]);
                }
        }

#pragma unroll
        for (int i = 0; i < 4; i++)
#pragma unroll
            for (int j = 0; j < 4; j++) {
                s[i][j] *= 0.125f;
                int kg = kt * 64 + j * 16 + tx;
                int qg = qt * 64 + q_lo + i;
                if (kg > qg) s[i][j] = -1e30f;
            }

        float p[4][4];
#pragma unroll
        for (int i = 0; i < 4; i++) {
            float mx = fmaxf(fmaxf(s[i][0], s[i][1]), fmaxf(s[i][2], s[i][3]));
#pragma unroll
            for (int off = 1; off < 16; off <<= 1)
                mx = fmaxf(mx, __shfl_xor_sync(0xffffffffu, mx, off));
            float mnew = fmaxf(m_i[i], mx);
            float corr = __expf(m_i[i] - mnew);
            m_i[i] = mnew;
            float rs = 0.f;
#pragma unroll
            for (int j = 0; j < 4; j++) {
                p[i][j] = __expf(s[i][j] - mnew);
                rs += p[i][j];
            }
#pragma unroll
            for (int off = 1; off < 16; off <<= 1)
                rs += __shfl_xor_sync(0xffffffffu, rs, off);
            l_i[i] = l_i[i] * corr + rs;
#pragma unroll
            for (int j = 0; j < 4; j++) acc[i][j] *= corr;
        }

        __syncthreads();
#pragma unroll
        for (int i = 0; i < 4; i++)
#pragma unroll
            for (int j = 0; j < 4; j++)
                KP[(q_lo + i) * 64 + j * 16 + tx] = p[i][j];
        __syncthreads();

#pragma unroll
        for (int k4 = 0; k4 < 16; k4++) {
            float4 pv[4];
#pragma unroll
            for (int i = 0; i < 4; i++)
                pv[i] = *(const float4*)&KP[(q_lo + i) * 64 + k4 * 4];
            float4 v0 = *(const float4*)&Vs[(k4 * 4 + 0) * 64 + tx * 4];
            float4 v1 = *(const float4*)&Vs[(k4 * 4 + 1) * 64 + tx * 4];
            float4 v2 = *(const float4*)&Vs[(k4 * 4 + 2) * 64 + tx * 4];
            float4 v3 = *(const float4*)&Vs[(k4 * 4 + 3) * 64 + tx * 4];
#pragma unroll
            for (int i = 0; i < 4; i++) {
                acc[i][0] = fmaf(pv[i].x, v0.x, acc[i][0]);
                acc[i][1] = fmaf(pv[i].x, v0.y, acc[i][1]);
                acc[i][2] = fmaf(pv[i].x, v0.z, acc[i][2]);
                acc[i][3] = fmaf(pv[i].x, v0.w, acc[i][3]);
                acc[i][0] = fmaf(pv[i].y, v1.x, acc[i][0]);
                acc[i][1] = fmaf(pv[i].y, v1.y, acc[i][1]);
                acc[i][2] = fmaf(pv[i].y, v1.z, acc[i][2]);
                acc[i][3] = fmaf(pv[i].y, v1.w, acc[i][3]);
                acc[i][0] = fmaf(pv[i].z, v2.x, acc[i][0]);
                acc[i][1] = fmaf(pv[i].z, v2.y, acc[i][1]);
                acc[i][2] = fmaf(pv[i].z, v2.z, acc[i][2]);
                acc[i][3] = fmaf(pv[i].z, v2.w, acc[i][3]);
                acc[i][0] = fmaf(pv[i].w, v3.x, acc[i][0]);
                acc[i][1] = fmaf(pv[i].w, v3.y, acc[i][1]);
                acc[i][2] = fmaf(pv[i].w, v3.z, acc[i][2]);
                acc[i][3] = fmaf(pv[i].w, v3.w, acc[i][3]);
            }
        }
    }

    float* ob = Oa + (size_t)(b * T_DIM + qt * 64) * C_DIM + h * DH_DIM;
#pragma unroll
    for (int i = 0; i < 4; i++) {
        float inv = 1.f / l_i[i];
        float4 o;
        o.x = acc[i][0] * inv;
        o.y = acc[i][1] * inv;
        o.z = acc[i][2] * inv;
        o.w = acc[i][3] * inv;
        *(float4*)&ob[(size_t)(q_lo + i) * C_DIM + tx * 4] = o;
    }
}

// ===========================================================================
// Launch
// ===========================================================================
extern "C" void kernel_launch(void* const* d_in, const int* in_sizes, int n_in,
                              void* d_out, int out_size)
{
    (void)in_sizes; (void)n_in; (void)out_size;
    const float* x  = (const float*)d_in[0];
    const float* Wq = (const float*)d_in[1];
    const float* Wk = (const float*)d_in[2];
    const float* Wv = (const float*)d_in[3];
    const float* Wo = (const float*)d_in[4];
    const float* bo = (const float*)d_in[5];
    float* out = (float*)d_out;

    float *pQ, *pK, *pV, *pAtt;
    __nv_bfloat16 *pXh, *pXl, *pAh, *pAl;
    __nv_bfloat16 *pWqh, *pWql, *pWkh, *pWkl, *pWvh, *pWvl, *pWoh, *pWol;
    cudaGetSymbolAddress((void**)&pQ,   g_Q);
    cudaGetSymbolAddress((void**)&pK,   g_K);
    cudaGetSymbolAddress((void**)&pV,   g_V);
    cudaGetSymbolAddress((void**)&pAtt, g_att);
    cudaGetSymbolAddress((void**)&pXh,  g_Xh);
    cudaGetSymbolAddress((void**)&pXl,  g_Xl);
    cudaGetSymbolAddress((void**)&pAh,  g_Ah);
    cudaGetSymbolAddress((void**)&pAl,  g_Al);
    cudaGetSymbolAddress((void**)&pWqh, g_Wqh);
    cudaGetSymbolAddress((void**)&pWql, g_Wql);
    cudaGetSymbolAddress((void**)&pWkh, g_Wkh);
    cudaGetSymbolAddress((void**)&pWkl, g_Wkl);
    cudaGetSymbolAddress((void**)&pWvh, g_Wvh);
    cudaGetSymbolAddress((void**)&pWvl, g_Wvl);
    cudaGetSymbolAddress((void**)&pWoh, g_Woh);
    cudaGetSymbolAddress((void**)&pWol, g_Wol);

    // 1. splits / weight prep
    prep_weights<<<(C_DIM * C_DIM) / 256, 256>>>(Wq, Wk, Wv, Wo);
    split_x<<<(M_DIM * C_DIM) / 256, 256>>>(x);

    // 2. QKV projections on tensor cores (bf16 hi/lo x3 compensation)
    dim3 gg(C_DIM / 128, M_DIM / 128);   // (8, 64)
    gemm_mma<<<gg, 256>>>(pXh, pXl, pWqh, pWql, pQ, nullptr, C_DIM, C_DIM);
    gemm_mma<<<gg, 256>>>(pXh, pXl, pWkh, pWkl, pK, nullptr, C_DIM, C_DIM);
    gemm_mma<<<gg, 256>>>(pXh, pXl, pWvh, pWvl, pV, nullptr, C_DIM, C_DIM);

    // 3. causal flash attention (fp32)
    attn_kernel<<<dim3(T_DIM / 64, H_DIM, B_DIM), 256>>>(pQ, pK, pV, pAtt);

    // 4. output projection (tensor cores) + bias
    split_att<<<(M_DIM * C_DIM) / 256, 256>>>();
    gemm_mma<<<gg, 256>>>(pAh, pAl, pWoh, pWol, out, bo, C_DIM, C_DIM);
}

// round 8
// speedup vs baseline: 2.3052x; 1.5203x over previous
#include <cuda_runtime.h>
#include <cuda_bf16.h>
#include <cstdint>

// Problem constants
#define C_DIM 1024
#define B_DIM 4
#define T_DIM 2048
#define H_DIM 16
#define DH_DIM 64
#define M_DIM (B_DIM * T_DIM)   // 8192

// ===========================================================================
// Scratch (__device__ globals; no cudaMalloc allowed)
// ===========================================================================
__device__ __nv_bfloat16  g_Xh [M_DIM * C_DIM];   // x hi/lo split
__device__ __nv_bfloat16  g_Xl [M_DIM * C_DIM];
__device__ __nv_bfloat16  g_Qh [M_DIM * C_DIM], g_Ql [M_DIM * C_DIM];
__device__ __nv_bfloat16  g_Kh [M_DIM * C_DIM], g_Kl [M_DIM * C_DIM];
__device__ __nv_bfloat16  g_Vh [M_DIM * C_DIM], g_Vl [M_DIM * C_DIM];
__device__ __nv_bfloat16  g_Ah [M_DIM * C_DIM], g_Al [M_DIM * C_DIM];
// weights as [N][K] bf16 hi/lo (B operand of mma .col = K-major [N,K] rows)
__device__ __nv_bfloat16  g_Wqh[C_DIM * C_DIM], g_Wql[C_DIM * C_DIM];
__device__ __nv_bfloat16  g_Wkh[C_DIM * C_DIM], g_Wkl[C_DIM * C_DIM];
__device__ __nv_bfloat16  g_Wvh[C_DIM * C_DIM], g_Wvl[C_DIM * C_DIM];
__device__ __nv_bfloat16  g_Woh[C_DIM * C_DIM], g_Wol[C_DIM * C_DIM];

__device__ __forceinline__ void split_bf16(float v, __nv_bfloat16& h, __nv_bfloat16& l) {
    __nv_bfloat16 hi = __float2bfloat16(v);
    h = hi;
    l = __float2bfloat16(v - __bfloat162float(hi));
}
__device__ __forceinline__ uint32_t pack2(__nv_bfloat16 lo, __nv_bfloat16 hi) {
    __nv_bfloat162 t(lo, hi);
    return reinterpret_cast<uint32_t&>(t);
}

// ---------------------------------------------------------------------------
// Weight prep: [H,C,DH] -> [n=h*64+d][c] bf16 hi/lo; Wo [j][c] is already [N][K].
// ---------------------------------------------------------------------------
__global__ void prep_weights(const float* __restrict__ Wq,
                             const float* __restrict__ Wk,
                             const float* __restrict__ Wv,
                             const float* __restrict__ Wo)
{
    int i = blockIdx.x * blockDim.x + threadIdx.x;   // i = n*1024 + c
    int n = i >> 10;
    int c = i & 1023;
    int h = n >> 6;
    int d = n & 63;
    int src = (h << 16) + (c << 6) + d;              // h*C*DH + c*DH + d
    split_bf16(Wq[src], g_Wqh[i], g_Wql[i]);
    split_bf16(Wk[src], g_Wkh[i], g_Wkl[i]);
    split_bf16(Wv[src], g_Wvh[i], g_Wvl[i]);
    split_bf16(Wo[i],   g_Woh[i], g_Wol[i]);
}

__global__ void split_x(const float* __restrict__ x)
{
    int i = blockIdx.x * blockDim.x + threadIdx.x;
    split_bf16(x[i], g_Xh[i], g_Xl[i]);
}

// ===========================================================================
// PTX wrappers (all plain sm_80+ — assemble under compute_103)
// ===========================================================================
__device__ __forceinline__ uint32_t smem_u32(const void* p) {
    uint32_t a;
    asm("{ .reg .u64 t; cvta.to.shared.u64 t, %1; cvt.u32.u64 %0, t; }"
        : "=r"(a) : "l"(p));
    return a;
}
__device__ __forceinline__ void ldsm4(uint32_t* r, uint32_t addr) {
    asm volatile("ldmatrix.sync.aligned.m8n8.x4.shared.b16 {%0,%1,%2,%3}, [%4];"
                 : "=r"(r[0]), "=r"(r[1]), "=r"(r[2]), "=r"(r[3]) : "r"(addr));
}
__device__ __forceinline__ void ldsm4t(uint32_t* r, uint32_t addr) {
    asm volatile("ldmatrix.sync.aligned.m8n8.x4.trans.shared.b16 {%0,%1,%2,%3}, [%4];"
                 : "=r"(r[0]), "=r"(r[1]), "=r"(r[2]), "=r"(r[3]) : "r"(addr));
}
__device__ __forceinline__ void mma16816(float* c, const uint32_t* a, const uint32_t* b) {
    asm volatile("mma.sync.aligned.m16n8k16.row.col.f32.bf16.bf16.f32 "
                 "{%0,%1,%2,%3}, {%4,%5,%6,%7}, {%8,%9}, {%0,%1,%2,%3};"
                 : "+f"(c[0]), "+f"(c[1]), "+f"(c[2]), "+f"(c[3])
                 : "r"(a[0]), "r"(a[1]), "r"(a[2]), "r"(a[3]),
                   "r"(b[0]), "r"(b[1]));
}
#define CP_ASYNC16(saddr, gptr) \
    asm volatile("cp.async.cg.shared.global [%0], [%1], 16;" \
                 :: "r"(saddr), "l"(gptr) : "memory")
#define CP_COMMIT()  asm volatile("cp.async.commit_group;" ::: "memory")
#define CP_WAIT0()   asm volatile("cp.async.wait_group 0;" ::: "memory")

// ===========================================================================
// bf16 hi/lo GEMM via mma.sync: C = A[M,K] * B[N,K]^T, 3-term compensation.
// Block 128x128, 8 warps (4m x 2n), warp tile 32x64, K-chunk 32, pitch 80B.
// Output: fp32 (+bias) if outh==null, else bf16 hi/lo split pair.
// ===========================================================================
#define PITCH   80
#define TILE_B  (128 * PITCH)          // 10240 bytes per tile
#define OA_H    0
#define OA_L    (TILE_B)
#define OB_H    (2 * TILE_B)
#define OB_L    (3 * TILE_B)

__global__ __launch_bounds__(256, 2)
void gemm_mma(const __nv_bfloat16* __restrict__ Ahp, const __nv_bfloat16* __restrict__ Alp,
              const __nv_bfloat16* __restrict__ Bhp, const __nv_bfloat16* __restrict__ Blp,
              float* __restrict__ Cmat, const float* __restrict__ bias,
              __nv_bfloat16* __restrict__ outh, __nv_bfloat16* __restrict__ outl,
              int Nglob, int Kglob)
{
    __shared__ char sm[4 * TILE_B];    // 40960 B static
    const uint32_t sb = smem_u32(sm);

    const int tid  = threadIdx.x;
    const int lane = tid & 31;
    const int wid  = tid >> 5;
    const int wm   = wid & 3;
    const int wn   = wid >> 2;

    const int row0 = blockIdx.y * 128;
    const int col0 = blockIdx.x * 128;

    const int r0g = tid >> 2;
    const int c0g = tid & 3;
    const __nv_bfloat16* pAh0 = Ahp + (size_t)(row0 + r0g) * Kglob + c0g * 8;
    const __nv_bfloat16* pAl0 = Alp + (size_t)(row0 + r0g) * Kglob + c0g * 8;
    const __nv_bfloat16* pBh0 = Bhp + (size_t)(col0 + r0g) * Kglob + c0g * 8;
    const __nv_bfloat16* pBl0 = Blp + (size_t)(col0 + r0g) * Kglob + c0g * 8;
    const size_t rowStep = (size_t)64 * Kglob;
    const uint32_t s0 = (uint32_t)(r0g * PITCH + c0g * 16);
    const uint32_t s1 = s0 + 64 * PITCH;

    const int a_row = (lane & 7) + ((lane >> 3) & 1) * 8;
    const int a_kb  = (lane >> 4);
    const int b_row = (lane & 7) + ((lane >> 4) & 1) * 8;
    const int b_kb  = (lane >> 3) & 1;

    float acc[2][8][4];
#pragma unroll
    for (int mi = 0; mi < 2; mi++)
#pragma unroll
        for (int nf = 0; nf < 8; nf++)
#pragma unroll
            for (int e = 0; e < 4; e++) acc[mi][nf][e] = 0.f;

    const int NCH = Kglob >> 5;
    for (int ch = 0; ch < NCH; ch++) {
        const int k0 = ch << 5;
        __syncthreads();

        CP_ASYNC16(sb + OA_H + s0, pAh0 + k0);
        CP_ASYNC16(sb + OA_H + s1, pAh0 + rowStep + k0);
        CP_ASYNC16(sb + OA_L + s0, pAl0 + k0);
        CP_ASYNC16(sb + OA_L + s1, pAl0 + rowStep + k0);
        CP_ASYNC16(sb + OB_H + s0, pBh0 + k0);
        CP_ASYNC16(sb + OB_H + s1, pBh0 + rowStep + k0);
        CP_ASYNC16(sb + OB_L + s0, pBl0 + k0);
        CP_ASYNC16(sb + OB_L + s1, pBl0 + rowStep + k0);
        CP_COMMIT();
        CP_WAIT0();
        __syncthreads();

#pragma unroll
        for (int ks = 0; ks < 2; ks++) {
            uint32_t ah[2][4], al[2][4], bh[4][4], bl[4][4];
#pragma unroll
            for (int mi = 0; mi < 2; mi++) {
                uint32_t ar = sb + (uint32_t)((wm * 32 + mi * 16 + a_row) * PITCH
                                              + (2 * ks + a_kb) * 16);
                ldsm4(ah[mi], ar + OA_H);
                ldsm4(al[mi], ar + OA_L);
            }
#pragma unroll
            for (int p = 0; p < 4; p++) {
                uint32_t br = sb + (uint32_t)((wn * 64 + p * 16 + b_row) * PITCH
                                              + (2 * ks + b_kb) * 16);
                ldsm4(bh[p], br + OB_H);
                ldsm4(bl[p], br + OB_L);
            }
#pragma unroll
            for (int mi = 0; mi < 2; mi++)
#pragma unroll
                for (int p = 0; p < 4; p++) {
                    mma16816(acc[mi][2 * p + 0], ah[mi], &bh[p][0]);
                    mma16816(acc[mi][2 * p + 0], ah[mi], &bl[p][0]);
                    mma16816(acc[mi][2 * p + 0], al[mi], &bh[p][0]);
                    mma16816(acc[mi][2 * p + 1], ah[mi], &bh[p][2]);
                    mma16816(acc[mi][2 * p + 1], ah[mi], &bl[p][2]);
                    mma16816(acc[mi][2 * p + 1], al[mi], &bh[p][2]);
                }
        }
    }

    const int tq = lane >> 2;
    const int tr = lane & 3;
#pragma unroll
    for (int mi = 0; mi < 2; mi++) {
        int rbase = row0 + wm * 32 + mi * 16 + tq;
#pragma unroll
        for (int nf = 0; nf < 8; nf++) {
            int col = col0 + wn * 64 + nf * 8 + tr * 2;
            if (outh) {
                __nv_bfloat16 h0, l0, h1, l1;
                split_bf16(acc[mi][nf][0], h0, l0);
                split_bf16(acc[mi][nf][1], h1, l1);
                *(uint32_t*)&outh[(size_t)rbase * Nglob + col] = pack2(h0, h1);
                *(uint32_t*)&outl[(size_t)rbase * Nglob + col] = pack2(l0, l1);
                split_bf16(acc[mi][nf][2], h0, l0);
                split_bf16(acc[mi][nf][3], h1, l1);
                *(uint32_t*)&outh[(size_t)(rbase + 8) * Nglob + col] = pack2(h0, h1);
                *(uint32_t*)&outl[(size_t)(rbase + 8) * Nglob + col] = pack2(l0, l1);
            } else {
                float bx = 0.f, by = 0.f;
                if (bias) { bx = bias[col]; by = bias[col + 1]; }
                float2 v0 = { acc[mi][nf][0] + bx, acc[mi][nf][1] + by };
                float2 v1 = { acc[mi][nf][2] + bx, acc[mi][nf][3] + by };
                *(float2*)&Cmat[(size_t)rbase * Nglob + col]       = v0;
                *(float2*)&Cmat[(size_t)(rbase + 8) * Nglob + col] = v1;
            }
        }
    }
}

// ===========================================================================
// Tensor-core causal flash attention, bf16 hi/lo compensated.
// q-tile 128 x k-tile 64, 8 warps (warp = m16 x full n64). Q frags preloaded
// to registers; K via non-trans ldsm (B operand), V via ldmatrix.x4.trans.
// S = QhKh+QhKl+QlKh; softmax in base-2 regs; P split hi/lo;
// O += PhVh+PhVl+PlVh. Pitch 144B smem (conflict-free), 36KB static.
// ===========================================================================
#define AP 144
#define Q_STAGE_L (128 * AP)           // 18432 (Qh at 0, Ql at Q_STAGE_L)
#define KV_T      (64 * AP)            // 9216: Kh 0 | Kl 9216 | Vh 18432 | Vl 27648

__global__ __launch_bounds__(256, 1)
void attn_mma(const __nv_bfloat16* __restrict__ Qh, const __nv_bfloat16* __restrict__ Ql,
              const __nv_bfloat16* __restrict__ Kh, const __nv_bfloat16* __restrict__ Kl,
              const __nv_bfloat16* __restrict__ Vh, const __nv_bfloat16* __restrict__ Vl,
              __nv_bfloat16* __restrict__ Ao_h, __nv_bfloat16* __restrict__ Ao_l)
{
    __shared__ char sm[2 * Q_STAGE_L];   // 36864 B
    const uint32_t sb = smem_u32(sm);

    const int tid  = threadIdx.x;
    const int lane = tid & 31;
    const int w    = tid >> 5;
    const int qt   = (int)gridDim.x - 1 - (int)blockIdx.x;   // big tiles first
    const int h    = blockIdx.y;
    const int b    = blockIdx.z;

    const int tq = lane >> 2;
    const int tr = lane & 3;
    const int a_row = (lane & 7) + ((lane >> 3) & 1) * 8;
    const int a_kb  = (lane >> 4);
    const int b_row = (lane & 7) + ((lane >> 4) & 1) * 8;
    const int b_kb  = (lane >> 3) & 1;

    // ---- stage Q hi/lo (128 rows x 64 bf16), preload frags to registers
    {
        const size_t qg0 = (size_t)(b * T_DIM + qt * 128) * C_DIM + h * DH_DIM;
#pragma unroll
        for (int k = 0; k < 4; k++) {
            int u = tid + k * 256;
            int r = u >> 3, c = u & 7;
            size_t ga = qg0 + (size_t)r * C_DIM + c * 8;
            uint32_t sa = (uint32_t)(r * AP + c * 16);
            CP_ASYNC16(sb + sa,             Qh + ga);
            CP_ASYNC16(sb + Q_STAGE_L + sa, Ql + ga);
        }
        CP_COMMIT();
        CP_WAIT0();
        __syncthreads();
    }
    uint32_t qfh[4][4], qfl[4][4];
#pragma unroll
    for (int ks = 0; ks < 4; ks++) {
        uint32_t ar = sb + (uint32_t)((w * 16 + a_row) * AP + ks * 32 + a_kb * 16);
        ldsm4(qfh[ks], ar);
        ldsm4(qfl[ks], ar + Q_STAGE_L);
    }
    __syncthreads();   // Q staging done; smem now reused for K/V

    float oacc[8][4];
#pragma unroll
    for (int nf = 0; nf < 8; nf++)
#pragma unroll
        for (int e = 0; e < 4; e++) oacc[nf][e] = 0.f;
    float m0 = -1e30f, m1 = -1e30f, l0 = 0.f, l1 = 0.f;

    const float SC = 0.18033688f;      // DH^-0.5 * log2(e)
    const size_t kvbase = (size_t)(b * T_DIM) * C_DIM + h * DH_DIM;
    const int ntiles = 2 * qt + 2;

    for (int kt = 0; kt < ntiles; kt++) {
        __syncthreads();               // previous tile fully consumed
        // load K/V hi/lo tiles (64 rows x 64 bf16 each)
#pragma unroll
        for (int k = 0; k < 2; k++) {
            int u = tid + k * 256;
            int r = u >> 3, c = u & 7;
            size_t ga = kvbase + (size_t)(kt * 64 + r) * C_DIM + c * 8;
            uint32_t sa = (uint32_t)(r * AP + c * 16);
            CP_ASYNC16(sb + 0 * KV_T + sa, Kh + ga);
            CP_ASYNC16(sb + 1 * KV_T + sa, Kl + ga);
            CP_ASYNC16(sb + 2 * KV_T + sa, Vh + ga);
            CP_ASYNC16(sb + 3 * KV_T + sa, Vl + ga);
        }
        CP_COMMIT();
        CP_WAIT0();
        __syncthreads();

        // ---- S = Q K^T (3-term)
        float sacc[8][4];
#pragma unroll
        for (int nf = 0; nf < 8; nf++)
#pragma unroll
            for (int e = 0; e < 4; e++) sacc[nf][e] = 0.f;

#pragma unroll
        for (int ks = 0; ks < 4; ks++) {
            uint32_t kh4[4][4], kl4[4][4];
#pragma unroll
            for (int p = 0; p < 4; p++) {
                uint32_t br = sb + (uint32_t)((p * 16 + b_row) * AP + ks * 32 + b_kb * 16);
                ldsm4(kh4[p], br);
                ldsm4(kl4[p], br + KV_T);
            }
#pragma unroll
            for (int p = 0; p < 4; p++) {
                mma16816(sacc[2 * p + 0], qfh[ks], &kh4[p][0]);
                mma16816(sacc[2 * p + 0], qfh[ks], &kl4[p][0]);
                mma16816(sacc[2 * p + 0], qfl[ks], &kh4[p][0]);
                mma16816(sacc[2 * p + 1], qfh[ks], &kh4[p][2]);
                mma16816(sacc[2 * p + 1], qfh[ks], &kl4[p][2]);
                mma16816(sacc[2 * p + 1], qfl[ks], &kh4[p][2]);
            }
        }

        // scale (base-2) + causal mask on diagonal tiles
        const bool need_mask = (kt >= 2 * qt);
#pragma unroll
        for (int nf = 0; nf < 8; nf++)
#pragma unroll
            for (int e = 0; e < 4; e++) {
                float s = sacc[nf][e] * SC;
                if (need_mask) {
                    int kg = kt * 64 + nf * 8 + 2 * tr + (e & 1);
                    int qg = qt * 128 + w * 16 + tq + ((e >> 1) << 3);
                    if (kg > qg) s = -1e30f;
                }
                sacc[nf][e] = s;
            }

        // row max (4-lane groups share a row)
        float mx0 = -1e30f, mx1 = -1e30f;
#pragma unroll
        for (int nf = 0; nf < 8; nf++) {
            mx0 = fmaxf(mx0, fmaxf(sacc[nf][0], sacc[nf][1]));
            mx1 = fmaxf(mx1, fmaxf(sacc[nf][2], sacc[nf][3]));
        }
        mx0 = fmaxf(mx0, __shfl_xor_sync(0xffffffffu, mx0, 1));
        mx0 = fmaxf(mx0, __shfl_xor_sync(0xffffffffu, mx0, 2));
        mx1 = fmaxf(mx1, __shfl_xor_sync(0xffffffffu, mx1, 1));
        mx1 = fmaxf(mx1, __shfl_xor_sync(0xffffffffu, mx1, 2));
        float mn0 = fmaxf(m0, mx0), mn1 = fmaxf(m1, mx1);
        float cr0 = exp2f(m0 - mn0), cr1 = exp2f(m1 - mn1);
        m0 = mn0; m1 = mn1;

        // exp + pack P as A-fragments (hi/lo)
        float rs0 = 0.f, rs1 = 0.f;
        uint32_t ph[4][4], pl[4][4];
#pragma unroll
        for (int kk = 0; kk < 4; kk++)
#pragma unroll
            for (int hh = 0; hh < 2; hh++) {
                int f = 2 * kk + hh;
                float e0 = exp2f(sacc[f][0] - mn0);
                float e1 = exp2f(sacc[f][1] - mn0);
                float e2 = exp2f(sacc[f][2] - mn1);
                float e3 = exp2f(sacc[f][3] - mn1);
                rs0 += e0 + e1;
                rs1 += e2 + e3;
                __nv_bfloat16 h0, q0, h1, q1, h2, q2, h3, q3;
                split_bf16(e0, h0, q0);
                split_bf16(e1, h1, q1);
                split_bf16(e2, h2, q2);
                split_bf16(e3, h3, q3);
                ph[kk][hh * 2 + 0] = pack2(h0, h1);
                ph[kk][hh * 2 + 1] = pack2(h2, h3);
                pl[kk][hh * 2 + 0] = pack2(q0, q1);
                pl[kk][hh * 2 + 1] = pack2(q2, q3);
            }
        rs0 += __shfl_xor_sync(0xffffffffu, rs0, 1);
        rs0 += __shfl_xor_sync(0xffffffffu, rs0, 2);
        rs1 += __shfl_xor_sync(0xffffffffu, rs1, 1);
        rs1 += __shfl_xor_sync(0xffffffffu, rs1, 2);
        l0 = l0 * cr0 + rs0;
        l1 = l1 * cr1 + rs1;
#pragma unroll
        for (int nf = 0; nf < 8; nf++) {
            oacc[nf][0] *= cr0;
            oacc[nf][1] *= cr0;
            oacc[nf][2] *= cr1;
            oacc[nf][3] *= cr1;
        }

        // ---- O += P V (3-term), V loaded transposed
#pragma unroll
        for (int kk = 0; kk < 4; kk++)
#pragma unroll
            for (int p = 0; p < 4; p++) {
                uint32_t va = sb + 2 * KV_T
                    + (uint32_t)((kk * 16 + (lane & 7) + ((lane >> 3) & 1) * 8) * AP
                                 + (p * 16 + (lane >> 4) * 8) * 2);
                uint32_t vh4[4], vl4[4];
                ldsm4t(vh4, va);
                ldsm4t(vl4, va + KV_T);
                mma16816(oacc[2 * p + 0], ph[kk], &vh4[0]);
                mma16816(oacc[2 * p + 0], ph[kk], &vl4[0]);
                mma16816(oacc[2 * p + 0], pl[kk], &vh4[0]);
                mma16816(oacc[2 * p + 1], ph[kk], &vh4[2]);
                mma16816(oacc[2 * p + 1], ph[kk], &vl4[2]);
                mma16816(oacc[2 * p + 1], pl[kk], &vh4[2]);
            }
    }

    // epilogue: normalize, split hi/lo, write [B,T, h*64+d]
    const float inv0 = 1.f / l0;
    const float inv1 = 1.f / l1;
    const size_t r0 = (size_t)(b * T_DIM + qt * 128 + w * 16 + tq);
    const size_t r1 = r0 + 8;
#pragma unroll
    for (int nf = 0; nf < 8; nf++) {
        int col = h * DH_DIM + nf * 8 + 2 * tr;
        __nv_bfloat16 h0, q0, h1, q1;
        split_bf16(oacc[nf][0] * inv0, h0, q0);
        split_bf16(oacc[nf][1] * inv0, h1, q1);
        *(uint32_t*)&Ao_h[r0 * C_DIM + col] = pack2(h0, h1);
        *(uint32_t*)&Ao_l[r0 * C_DIM + col] = pack2(q0, q1);
        split_bf16(oacc[nf][2] * inv1, h0, q0);
        split_bf16(oacc[nf][3] * inv1, h1, q1);
        *(uint32_t*)&Ao_h[r1 * C_DIM + col] = pack2(h0, h1);
        *(uint32_t*)&Ao_l[r1 * C_DIM + col] = pack2(q0, q1);
    }
}

// ===========================================================================
// Launch
// ===========================================================================
extern "C" void kernel_launch(void* const* d_in, const int* in_sizes, int n_in,
                              void* d_out, int out_size)
{
    (void)in_sizes; (void)n_in; (void)out_size;
    const float* x  = (const float*)d_in[0];
    const float* Wq = (const float*)d_in[1];
    const float* Wk = (const float*)d_in[2];
    const float* Wv = (const float*)d_in[3];
    const float* Wo = (const float*)d_in[4];
    const float* bo = (const float*)d_in[5];
    float* out = (float*)d_out;

    __nv_bfloat16 *pXh, *pXl, *pAh, *pAl;
    __nv_bfloat16 *pQh, *pQl, *pKh, *pKl, *pVh, *pVl;
    __nv_bfloat16 *pWqh, *pWql, *pWkh, *pWkl, *pWvh, *pWvl, *pWoh, *pWol;
    cudaGetSymbolAddress((void**)&pXh,  g_Xh);
    cudaGetSymbolAddress((void**)&pXl,  g_Xl);
    cudaGetSymbolAddress((void**)&pAh,  g_Ah);
    cudaGetSymbolAddress((void**)&pAl,  g_Al);
    cudaGetSymbolAddress((void**)&pQh,  g_Qh);
    cudaGetSymbolAddress((void**)&pQl,  g_Ql);
    cudaGetSymbolAddress((void**)&pKh,  g_Kh);
    cudaGetSymbolAddress((void**)&pKl,  g_Kl);
    cudaGetSymbolAddress((void**)&pVh,  g_Vh);
    cudaGetSymbolAddress((void**)&pVl,  g_Vl);
    cudaGetSymbolAddress((void**)&pWqh, g_Wqh);
    cudaGetSymbolAddress((void**)&pWql, g_Wql);
    cudaGetSymbolAddress((void**)&pWkh, g_Wkh);
    cudaGetSymbolAddress((void**)&pWkl, g_Wkl);
    cudaGetSymbolAddress((void**)&pWvh, g_Wvh);
    cudaGetSymbolAddress((void**)&pWvl, g_Wvl);
    cudaGetSymbolAddress((void**)&pWoh, g_Woh);
    cudaGetSymbolAddress((void**)&pWol, g_Wol);

    // 1. splits / weight prep
    prep_weights<<<(C_DIM * C_DIM) / 256, 256>>>(Wq, Wk, Wv, Wo);
    split_x<<<(M_DIM * C_DIM) / 256, 256>>>(x);

    // 2. QKV projections -> bf16 hi/lo directly
    dim3 gg(C_DIM / 128, M_DIM / 128);   // (8, 64)
    gemm_mma<<<gg, 256>>>(pXh, pXl, pWqh, pWql, nullptr, nullptr, pQh, pQl, C_DIM, C_DIM);
    gemm_mma<<<gg, 256>>>(pXh, pXl, pWkh, pWkl, nullptr, nullptr, pKh, pKl, C_DIM, C_DIM);
    gemm_mma<<<gg, 256>>>(pXh, pXl, pWvh, pWvl, nullptr, nullptr, pVh, pVl, C_DIM, C_DIM);

    // 3. tensor-core causal flash attention -> bf16 hi/lo
    attn_mma<<<dim3(T_DIM / 128, H_DIM, B_DIM), 256>>>(pQh, pQl, pKh, pKl, pVh, pVl, pAh, pAl);

    // 4. output projection (fp32 out + bias)
    gemm_mma<<<gg, 256>>>(pAh, pAl, pWoh, pWol, out, bo, nullptr, nullptr, C_DIM, C_DIM);
}